// round 1
// baseline (speedup 1.0000x reference)
#include <cuda_runtime.h>
#include <math.h>

#define B_   2
#define S_   1024
#define D_   1024
#define H_   16
#define DK_  64
#define DFF_ 2048
#define L_   4
#define BS_  (B_*S_)

// ---------------- scratch (device globals; no allocations allowed) ----------
__device__ float g_x[BS_*D_];
__device__ float g_q[BS_*D_];
__device__ float g_k[BS_*D_];
__device__ float g_v[BS_*D_];
__device__ float g_o[BS_*D_];
__device__ float g_h[BS_*DFF_];
__device__ float g_f[BS_*D_];

__device__ __forceinline__ float gelu_tanh_f(float x) {
    float x3 = x * x * x;
    return 0.5f * x * (1.0f + tanhf(0.7978845608028654f * (x + 0.044715f * x3)));
}

// ---------------- generic NN GEMM: C[M,N] = A[M,K] @ W[K,N], epilogue -------
// EPI: 0 = none, 1 = +bias, 2 = gelu(+bias)
// 64x64 tile, BK=16, 256 threads, 4x4 per thread.
template<int EPI>
__global__ void gemm_nn(const float* __restrict__ A, const float* __restrict__ W,
                        const float* __restrict__ bias, float* __restrict__ C,
                        int N, int K) {
    __shared__ float As[16][64];
    __shared__ float Bs[16][64];
    int tid = threadIdx.x;
    int tx = tid & 15, ty = tid >> 4;
    int row0 = blockIdx.y * 64, col0 = blockIdx.x * 64;

    float acc[4][4] = {};
    for (int kt = 0; kt < K; kt += 16) {
        #pragma unroll
        for (int i = tid; i < 64*16; i += 256) {
            int m = i >> 4, k = i & 15;
            As[k][m] = A[(size_t)(row0 + m) * K + kt + k];
        }
        #pragma unroll
        for (int i = tid; i < 16*64; i += 256) {
            int k = i >> 6, n = i & 63;
            Bs[k][n] = W[(size_t)(kt + k) * N + col0 + n];
        }
        __syncthreads();
        #pragma unroll
        for (int k = 0; k < 16; k++) {
            float4 a = *(const float4*)&As[k][ty * 4];
            float4 b = *(const float4*)&Bs[k][tx * 4];
            float av[4] = {a.x, a.y, a.z, a.w};
            float bv[4] = {b.x, b.y, b.z, b.w};
            #pragma unroll
            for (int i = 0; i < 4; i++)
                #pragma unroll
                for (int j = 0; j < 4; j++)
                    acc[i][j] += av[i] * bv[j];
        }
        __syncthreads();
    }
    #pragma unroll
    for (int i = 0; i < 4; i++) {
        int row = row0 + ty * 4 + i;
        int col = col0 + tx * 4;
        float4 v;
        float r[4];
        #pragma unroll
        for (int j = 0; j < 4; j++) {
            float t = acc[i][j];
            if (EPI >= 1) t += bias[col + j];
            if (EPI == 2) t = gelu_tanh_f(t);
            r[j] = t;
        }
        v.x = r[0]; v.y = r[1]; v.z = r[2]; v.w = r[3];
        *(float4*)&C[(size_t)row * N + col] = v;
    }
}

// -------- attention scores: per z=(b*H+h), S[i,j]=scale*Q_i·K_j + bias, mask
__global__ void attn_scores(const float* __restrict__ attn_bias,
                            const int* __restrict__ mask,
                            float* __restrict__ out) {
    __shared__ float As[16][64];
    __shared__ float Bs[16][64];
    int tid = threadIdx.x;
    int tx = tid & 15, ty = tid >> 4;
    int row0 = blockIdx.y * 64, col0 = blockIdx.x * 64;
    int z = blockIdx.z;          // b*H + h
    int b = z >> 4;              // /H_
    int h = z & 15;

    const float* Q = g_q + (size_t)b * S_ * D_ + h * DK_;
    const float* Kp = g_k + (size_t)b * S_ * D_ + h * DK_;

    float acc[4][4] = {};
    for (int kt = 0; kt < DK_; kt += 16) {
        #pragma unroll
        for (int i = tid; i < 64*16; i += 256) {
            int m = i >> 4, k = i & 15;
            As[k][m] = Q[(size_t)(row0 + m) * D_ + kt + k];
        }
        #pragma unroll
        for (int i = tid; i < 64*16; i += 256) {
            int n = i >> 4, k = i & 15;
            Bs[k][n] = Kp[(size_t)(col0 + n) * D_ + kt + k];
        }
        __syncthreads();
        #pragma unroll
        for (int k = 0; k < 16; k++) {
            float4 a = *(const float4*)&As[k][ty * 4];
            float4 bb = *(const float4*)&Bs[k][tx * 4];
            float av[4] = {a.x, a.y, a.z, a.w};
            float bv[4] = {bb.x, bb.y, bb.z, bb.w};
            #pragma unroll
            for (int i = 0; i < 4; i++)
                #pragma unroll
                for (int j = 0; j < 4; j++)
                    acc[i][j] += av[i] * bv[j];
        }
        __syncthreads();
    }
    const float scale = 0.125f;  // 1/sqrt(64)
    const float* biasM = attn_bias + (size_t)z * S_ * S_;
    float* Cm = out + (size_t)z * S_ * S_;
    #pragma unroll
    for (int i = 0; i < 4; i++) {
        int row = row0 + ty * 4 + i;
        #pragma unroll
        for (int j = 0; j < 4; j++) {
            int col = col0 + tx * 4 + j;
            float v;
            if (mask[b * S_ + col] != 0)
                v = acc[i][j] * scale + biasM[(size_t)row * S_ + col];
            else
                v = -9e15f;
            Cm[(size_t)row * S_ + col] = v;
        }
    }
}

// ---------------- row softmax over S=1024, in place -------------------------
__global__ void softmax_rows(float* __restrict__ p) {
    float* row = p + (size_t)blockIdx.x * S_;
    __shared__ float red[256];
    int t = threadIdx.x;
    float v[4];
    float m = -INFINITY;
    #pragma unroll
    for (int i = 0; i < 4; i++) { v[i] = row[t + i * 256]; m = fmaxf(m, v[i]); }
    red[t] = m; __syncthreads();
    for (int s = 128; s > 0; s >>= 1) {
        if (t < s) red[t] = fmaxf(red[t], red[t + s]);
        __syncthreads();
    }
    m = red[0]; __syncthreads();
    float sum = 0.f;
    #pragma unroll
    for (int i = 0; i < 4; i++) { v[i] = __expf(v[i] - m); sum += v[i]; }
    red[t] = sum; __syncthreads();
    for (int s = 128; s > 0; s >>= 1) {
        if (t < s) red[t] += red[t + s];
        __syncthreads();
    }
    float inv = 1.0f / red[0];
    #pragma unroll
    for (int i = 0; i < 4; i++) row[t + i * 256] = v[i] * inv;
}

// ---------------- O[b,s,h*64+d] = sum_k P[z][s,k] * V[b,k,h*64+d] -----------
__global__ void attn_pv(const float* __restrict__ p) {
    __shared__ float As[16][64];
    __shared__ float Bs[16][64];
    int tid = threadIdx.x;
    int tx = tid & 15, ty = tid >> 4;
    int row0 = blockIdx.y * 64;
    int z = blockIdx.z;
    int b = z >> 4, h = z & 15;

    const float* A = p + (size_t)z * S_ * S_;
    const float* V = g_v + (size_t)b * S_ * D_ + h * DK_;

    float acc[4][4] = {};
    for (int kt = 0; kt < S_; kt += 16) {
        #pragma unroll
        for (int i = tid; i < 64*16; i += 256) {
            int m = i >> 4, k = i & 15;
            As[k][m] = A[(size_t)(row0 + m) * S_ + kt + k];
        }
        #pragma unroll
        for (int i = tid; i < 16*64; i += 256) {
            int k = i >> 6, n = i & 63;
            Bs[k][n] = V[(size_t)(kt + k) * D_ + n];
        }
        __syncthreads();
        #pragma unroll
        for (int k = 0; k < 16; k++) {
            float4 a = *(const float4*)&As[k][ty * 4];
            float4 bb = *(const float4*)&Bs[k][tx * 4];
            float av[4] = {a.x, a.y, a.z, a.w};
            float bv[4] = {bb.x, bb.y, bb.z, bb.w};
            #pragma unroll
            for (int i = 0; i < 4; i++)
                #pragma unroll
                for (int j = 0; j < 4; j++)
                    acc[i][j] += av[i] * bv[j];
        }
        __syncthreads();
    }
    float* O = g_o + (size_t)b * S_ * D_ + h * DK_;
    #pragma unroll
    for (int i = 0; i < 4; i++) {
        int row = row0 + ty * 4 + i;
        float4 v;
        v.x = acc[i][0]; v.y = acc[i][1]; v.z = acc[i][2]; v.w = acc[i][3];
        *(float4*)&O[(size_t)row * D_ + tx * 4] = v;
    }
}

// ---------------- x = LayerNorm(x + r) * g + b (in place on g_x) ------------
__global__ void add_ln(float* __restrict__ x, const float* __restrict__ r,
                       const float* __restrict__ g, const float* __restrict__ bb) {
    float* row = x + (size_t)blockIdx.x * D_;
    const float* rr = r + (size_t)blockIdx.x * D_;
    __shared__ float red[256];
    __shared__ float red2[256];
    int t = threadIdx.x;
    float v[4];
    float s = 0.f, s2 = 0.f;
    #pragma unroll
    for (int i = 0; i < 4; i++) {
        v[i] = row[t + i * 256] + rr[t + i * 256];
        s += v[i]; s2 += v[i] * v[i];
    }
    red[t] = s; red2[t] = s2; __syncthreads();
    for (int st = 128; st > 0; st >>= 1) {
        if (t < st) { red[t] += red[t + st]; red2[t] += red2[t + st]; }
        __syncthreads();
    }
    float mu = red[0] * (1.0f / D_);
    float var = red2[0] * (1.0f / D_) - mu * mu;
    float inv = rsqrtf(var + 1e-6f);
    #pragma unroll
    for (int i = 0; i < 4; i++) {
        int c = t + i * 256;
        row[c] = (v[i] - mu) * inv * g[c] + bb[c];
    }
}

__global__ void copyk(float* __restrict__ dst, const float* __restrict__ src, int n) {
    int i = blockIdx.x * 256 + threadIdx.x;
    if (i < n) dst[i] = src[i];
}

// ---------------------------------------------------------------------------
extern "C" void kernel_launch(void* const* d_in, const int* in_sizes, int n_in,
                              void* d_out, int out_size) {
    const float* x_in      = (const float*)d_in[0];
    const int*   mask      = (const int*)d_in[1];
    const float* attn_bias = (const float*)d_in[2];
    const float* Wq        = (const float*)d_in[3];
    const float* Wk        = (const float*)d_in[4];
    const float* Wv        = (const float*)d_in[5];
    const float* ln1_g     = (const float*)d_in[6];
    const float* ln1_b     = (const float*)d_in[7];
    const float* W1        = (const float*)d_in[8];
    const float* b1        = (const float*)d_in[9];
    const float* W2        = (const float*)d_in[10];
    const float* b2        = (const float*)d_in[11];
    const float* ln2_g     = (const float*)d_in[12];
    const float* ln2_b     = (const float*)d_in[13];
    float* out = (float*)d_out;

    float *px, *pq, *pk, *pv, *po, *ph, *pf;
    cudaGetSymbolAddress((void**)&px, g_x);
    cudaGetSymbolAddress((void**)&pq, g_q);
    cudaGetSymbolAddress((void**)&pk, g_k);
    cudaGetSymbolAddress((void**)&pv, g_v);
    cudaGetSymbolAddress((void**)&po, g_o);
    cudaGetSymbolAddress((void**)&ph, g_h);
    cudaGetSymbolAddress((void**)&pf, g_f);

    const int nX = BS_ * D_;
    copyk<<<(nX + 255) / 256, 256>>>(px, x_in, nX);

    dim3 gQKV(D_ / 64, BS_ / 64);        // 16 x 32
    dim3 gFF1(DFF_ / 64, BS_ / 64);      // 32 x 32
    dim3 gFF2(D_ / 64, BS_ / 64);        // 16 x 32
    dim3 gSc(S_ / 64, S_ / 64, B_ * H_); // 16 x 16 x 32
    dim3 gPV(1, S_ / 64, B_ * H_);       // 1 x 16 x 32

    for (int n = 0; n < L_; n++) {
        const float* wq = Wq + (size_t)n * D_ * D_;
        const float* wk = Wk + (size_t)n * D_ * D_;
        const float* wv = Wv + (size_t)n * D_ * D_;
        float* scores = out + (size_t)n * B_ * H_ * S_ * S_;

        gemm_nn<0><<<gQKV, 256>>>(px, wq, nullptr, pq, D_, D_);
        gemm_nn<0><<<gQKV, 256>>>(px, wk, nullptr, pk, D_, D_);
        gemm_nn<0><<<gQKV, 256>>>(px, wv, nullptr, pv, D_, D_);

        attn_scores<<<gSc, 256>>>(attn_bias, mask, scores);
        softmax_rows<<<B_ * H_ * S_, 256>>>(scores);
        attn_pv<<<gPV, 256>>>(scores);

        add_ln<<<BS_, 256>>>(px, po, ln1_g + n * D_, ln1_b + n * D_);

        gemm_nn<2><<<gFF1, 256>>>(px, W1 + (size_t)n * D_ * DFF_, b1 + n * DFF_, ph, DFF_, D_);
        gemm_nn<1><<<gFF2, 256>>>(ph, W2 + (size_t)n * DFF_ * D_, b2 + n * D_, pf, D_, DFF_);

        add_ln<<<BS_, 256>>>(px, pf, ln2_g + n * D_, ln2_b + n * D_);
    }

    copyk<<<(nX + 255) / 256, 256>>>(out + (size_t)L_ * B_ * H_ * S_ * S_, px, nX);
}

// round 2
// speedup vs baseline: 3.4352x; 3.4352x over previous
#include <cuda_runtime.h>
#include <stdint.h>
#include <math.h>

#define B_   2
#define S_   1024
#define D_   1024
#define H_   16
#define DK_  64
#define DFF_ 2048
#define L_   4
#define BS_  (B_*S_)

// ---------------- scratch ----------------------------------------------------
__device__ float g_x[BS_*D_];
__device__ float g_q[BS_*D_];
__device__ float g_k[BS_*D_];
__device__ float g_v[BS_*D_];
__device__ float g_o[BS_*D_];
__device__ float g_h[BS_*DFF_];
__device__ float g_f[BS_*D_];

__device__ __forceinline__ float gelu_tanh_f(float x) {
    float x3 = x * x * x;
    return 0.5f * x * (1.0f + tanhf(0.7978845608028654f * (x + 0.044715f * x3)));
}

__device__ __forceinline__ uint32_t f2tf(float f) {
    uint32_t u;
    asm("cvt.rna.tf32.f32 %0, %1;" : "=r"(u) : "f"(f));
    return u;
}

__device__ __forceinline__ void mma_tf32(float* c, const uint32_t* a, const uint32_t* b) {
    asm volatile(
        "mma.sync.aligned.m16n8k8.row.col.f32.tf32.tf32.f32 "
        "{%0,%1,%2,%3}, {%4,%5,%6,%7}, {%8,%9}, {%0,%1,%2,%3};"
        : "+f"(c[0]), "+f"(c[1]), "+f"(c[2]), "+f"(c[3])
        : "r"(a[0]), "r"(a[1]), "r"(a[2]), "r"(a[3]), "r"(b[0]), "r"(b[1]));
}

// =============================================================================
// Weights-style GEMM: C[M,N] = A[M,K] @ B[K,N]  (A row-major lda=K, B row-major ldb=N)
// 128x128 tile, BK=32, 256 thr, 8 warps (2Mx4N), warp 64x32, mma m16n8k8 tf32.
// EPI: 0 none, 1 +bias, 2 gelu(+bias)
// =============================================================================
template<int EPI>
__global__ __launch_bounds__(256, 2)
void gemm_tc(const float* __restrict__ A, const float* __restrict__ Bw,
             const float* __restrict__ bias, float* __restrict__ C,
             int N, int K) {
    __shared__ uint32_t As[32][133];   // [k][m], pad 5
    __shared__ uint32_t Bs[32][132];   // [k][n], pad 4 (16B aligned rows)
    const int tid = threadIdx.x;
    const int row0 = blockIdx.y * 128, col0 = blockIdx.x * 128;
    const int w = tid >> 5, lane = tid & 31;
    const int wm = w >> 2, wn = w & 3;          // 2 x 4 warps
    const int grp = lane >> 2, qd = lane & 3;

    float acc[4][4][4] = {};
    for (int kt = 0; kt < K; kt += 32) {
        #pragma unroll
        for (int i = 0; i < 4; i++) {
            int idx = tid + i * 256;
            int m = idx >> 3, k4 = (idx & 7) * 4;
            float4 v = *(const float4*)&A[(size_t)(row0 + m) * K + kt + k4];
            As[k4 + 0][m] = f2tf(v.x); As[k4 + 1][m] = f2tf(v.y);
            As[k4 + 2][m] = f2tf(v.z); As[k4 + 3][m] = f2tf(v.w);
        }
        #pragma unroll
        for (int i = 0; i < 4; i++) {
            int idx = tid + i * 256;
            int k = idx >> 5, n4 = (idx & 31) * 4;
            float4 v = *(const float4*)&Bw[(size_t)(kt + k) * N + col0 + n4];
            uint4 u = make_uint4(f2tf(v.x), f2tf(v.y), f2tf(v.z), f2tf(v.w));
            *(uint4*)&Bs[k][n4] = u;
        }
        __syncthreads();
        #pragma unroll
        for (int kk = 0; kk < 4; kk++) {
            int kb = kk * 8;
            uint32_t af[4][4], bf[4][2];
            #pragma unroll
            for (int mf = 0; mf < 4; mf++) {
                int r = wm * 64 + mf * 16 + grp;
                af[mf][0] = As[kb + qd][r];     af[mf][1] = As[kb + qd][r + 8];
                af[mf][2] = As[kb + qd + 4][r]; af[mf][3] = As[kb + qd + 4][r + 8];
            }
            #pragma unroll
            for (int nf = 0; nf < 4; nf++) {
                int c = wn * 32 + nf * 8 + grp;
                bf[nf][0] = Bs[kb + qd][c]; bf[nf][1] = Bs[kb + qd + 4][c];
            }
            #pragma unroll
            for (int mf = 0; mf < 4; mf++)
                #pragma unroll
                for (int nf = 0; nf < 4; nf++)
                    mma_tf32(acc[mf][nf], af[mf], bf[nf]);
        }
        __syncthreads();
    }
    #pragma unroll
    for (int mf = 0; mf < 4; mf++) {
        int r = row0 + wm * 64 + mf * 16 + grp;
        #pragma unroll
        for (int nf = 0; nf < 4; nf++) {
            int c = col0 + wn * 32 + nf * 8 + 2 * qd;
            float* a = acc[mf][nf];
            float v0 = a[0], v1 = a[1], v2 = a[2], v3 = a[3];
            if (EPI >= 1) {
                float b0 = bias[c], b1 = bias[c + 1];
                v0 += b0; v1 += b1; v2 += b0; v3 += b1;
            }
            if (EPI == 2) {
                v0 = gelu_tanh_f(v0); v1 = gelu_tanh_f(v1);
                v2 = gelu_tanh_f(v2); v3 = gelu_tanh_f(v3);
            }
            C[(size_t)r * N + c] = v0;       C[(size_t)r * N + c + 1] = v1;
            C[(size_t)(r + 8) * N + c] = v2; C[(size_t)(r + 8) * N + c + 1] = v3;
        }
    }
}

// =============================================================================
// Attention scores: per z=(b,h): S = scale * Q K^T + bias, masked. 128x128 tile.
// =============================================================================
__global__ __launch_bounds__(256, 2)
void score_tc(const float* __restrict__ attn_bias, const int* __restrict__ mask,
              float* __restrict__ out) {
    __shared__ uint32_t As[32][133];
    __shared__ uint32_t Bs[32][133];
    const int tid = threadIdx.x;
    const int row0 = blockIdx.y * 128, col0 = blockIdx.x * 128;
    const int z = blockIdx.z, b = z >> 4, h = z & 15;
    const int w = tid >> 5, lane = tid & 31;
    const int wm = w >> 2, wn = w & 3;
    const int grp = lane >> 2, qd = lane & 3;

    const float* Q = g_q + (size_t)b * S_ * D_ + h * DK_;
    const float* Kp = g_k + (size_t)b * S_ * D_ + h * DK_;

    float acc[4][4][4] = {};
    #pragma unroll
    for (int kt = 0; kt < DK_; kt += 32) {
        #pragma unroll
        for (int i = 0; i < 4; i++) {
            int idx = tid + i * 256;
            int m = idx >> 3, k4 = (idx & 7) * 4;
            float4 v = *(const float4*)&Q[(size_t)(row0 + m) * D_ + kt + k4];
            As[k4 + 0][m] = f2tf(v.x); As[k4 + 1][m] = f2tf(v.y);
            As[k4 + 2][m] = f2tf(v.z); As[k4 + 3][m] = f2tf(v.w);
        }
        #pragma unroll
        for (int i = 0; i < 4; i++) {
            int idx = tid + i * 256;
            int n = idx >> 3, k4 = (idx & 7) * 4;
            float4 v = *(const float4*)&Kp[(size_t)(col0 + n) * D_ + kt + k4];
            Bs[k4 + 0][n] = f2tf(v.x); Bs[k4 + 1][n] = f2tf(v.y);
            Bs[k4 + 2][n] = f2tf(v.z); Bs[k4 + 3][n] = f2tf(v.w);
        }
        __syncthreads();
        #pragma unroll
        for (int kk = 0; kk < 4; kk++) {
            int kb = kk * 8;
            uint32_t af[4][4], bf[4][2];
            #pragma unroll
            for (int mf = 0; mf < 4; mf++) {
                int r = wm * 64 + mf * 16 + grp;
                af[mf][0] = As[kb + qd][r];     af[mf][1] = As[kb + qd][r + 8];
                af[mf][2] = As[kb + qd + 4][r]; af[mf][3] = As[kb + qd + 4][r + 8];
            }
            #pragma unroll
            for (int nf = 0; nf < 4; nf++) {
                int c = wn * 32 + nf * 8 + grp;
                bf[nf][0] = Bs[kb + qd][c]; bf[nf][1] = Bs[kb + qd + 4][c];
            }
            #pragma unroll
            for (int mf = 0; mf < 4; mf++)
                #pragma unroll
                for (int nf = 0; nf < 4; nf++)
                    mma_tf32(acc[mf][nf], af[mf], bf[nf]);
        }
        __syncthreads();
    }
    const float scale = 0.125f;
    const float* biasM = attn_bias + (size_t)z * S_ * S_;
    float* Cm = out + (size_t)z * S_ * S_;
    #pragma unroll
    for (int mf = 0; mf < 4; mf++) {
        int r = row0 + wm * 64 + mf * 16 + grp;
        #pragma unroll
        for (int nf = 0; nf < 4; nf++) {
            int c = col0 + wn * 32 + nf * 8 + 2 * qd;
            float* a = acc[mf][nf];
            int mk0 = mask[b * S_ + c], mk1 = mask[b * S_ + c + 1];
            float o00 = mk0 ? a[0] * scale + biasM[(size_t)r * S_ + c]       : -9e15f;
            float o01 = mk1 ? a[1] * scale + biasM[(size_t)r * S_ + c + 1]   : -9e15f;
            float o10 = mk0 ? a[2] * scale + biasM[(size_t)(r+8) * S_ + c]   : -9e15f;
            float o11 = mk1 ? a[3] * scale + biasM[(size_t)(r+8) * S_ + c+1] : -9e15f;
            Cm[(size_t)r * S_ + c] = o00;       Cm[(size_t)r * S_ + c + 1] = o01;
            Cm[(size_t)(r + 8) * S_ + c] = o10; Cm[(size_t)(r + 8) * S_ + c + 1] = o11;
        }
    }
}

// =============================================================================
// PV: per z: O_slice[S,64] = P[S,S] @ V_slice[S,64]. 128x64 tile, 8 warps 4Mx2N.
// =============================================================================
__global__ __launch_bounds__(256, 2)
void pv_tc(const float* __restrict__ p) {
    __shared__ uint32_t As[32][133];
    __shared__ uint32_t Bs[32][68];
    const int tid = threadIdx.x;
    const int row0 = blockIdx.y * 128;
    const int z = blockIdx.z, b = z >> 4, h = z & 15;
    const int w = tid >> 5, lane = tid & 31;
    const int wm = w >> 1, wn = w & 1;          // 4 x 2 warps, warp tile 32x32
    const int grp = lane >> 2, qd = lane & 3;

    const float* A = p + (size_t)z * S_ * S_;
    const float* V = g_v + (size_t)b * S_ * D_ + h * DK_;

    float acc[2][4][4] = {};
    for (int kt = 0; kt < S_; kt += 32) {
        #pragma unroll
        for (int i = 0; i < 4; i++) {
            int idx = tid + i * 256;
            int m = idx >> 3, k4 = (idx & 7) * 4;
            float4 v = *(const float4*)&A[(size_t)(row0 + m) * S_ + kt + k4];
            As[k4 + 0][m] = f2tf(v.x); As[k4 + 1][m] = f2tf(v.y);
            As[k4 + 2][m] = f2tf(v.z); As[k4 + 3][m] = f2tf(v.w);
        }
        #pragma unroll
        for (int i = 0; i < 2; i++) {
            int idx = tid + i * 256;
            int k = idx >> 4, n4 = (idx & 15) * 4;
            float4 v = *(const float4*)&V[(size_t)(kt + k) * D_ + n4];
            uint4 u = make_uint4(f2tf(v.x), f2tf(v.y), f2tf(v.z), f2tf(v.w));
            *(uint4*)&Bs[k][n4] = u;
        }
        __syncthreads();
        #pragma unroll
        for (int kk = 0; kk < 4; kk++) {
            int kb = kk * 8;
            uint32_t af[2][4], bf[4][2];
            #pragma unroll
            for (int mf = 0; mf < 2; mf++) {
                int r = wm * 32 + mf * 16 + grp;
                af[mf][0] = As[kb + qd][r];     af[mf][1] = As[kb + qd][r + 8];
                af[mf][2] = As[kb + qd + 4][r]; af[mf][3] = As[kb + qd + 4][r + 8];
            }
            #pragma unroll
            for (int nf = 0; nf < 4; nf++) {
                int c = wn * 32 + nf * 8 + grp;
                bf[nf][0] = Bs[kb + qd][c]; bf[nf][1] = Bs[kb + qd + 4][c];
            }
            #pragma unroll
            for (int mf = 0; mf < 2; mf++)
                #pragma unroll
                for (int nf = 0; nf < 4; nf++)
                    mma_tf32(acc[mf][nf], af[mf], bf[nf]);
        }
        __syncthreads();
    }
    float* O = g_o + (size_t)b * S_ * D_ + h * DK_;
    #pragma unroll
    for (int mf = 0; mf < 2; mf++) {
        int r = row0 + wm * 32 + mf * 16 + grp;
        #pragma unroll
        for (int nf = 0; nf < 4; nf++) {
            int c = wn * 32 + nf * 8 + 2 * qd;
            float* a = acc[mf][nf];
            O[(size_t)r * D_ + c] = a[0];       O[(size_t)r * D_ + c + 1] = a[1];
            O[(size_t)(r + 8) * D_ + c] = a[2]; O[(size_t)(r + 8) * D_ + c + 1] = a[3];
        }
    }
}

// ---------------- row softmax over S=1024, in place -------------------------
__global__ void softmax_rows(float* __restrict__ p) {
    float* row = p + (size_t)blockIdx.x * S_;
    __shared__ float red[256];
    int t = threadIdx.x;
    float v[4];
    float m = -INFINITY;
    #pragma unroll
    for (int i = 0; i < 4; i++) { v[i] = row[t + i * 256]; m = fmaxf(m, v[i]); }
    red[t] = m; __syncthreads();
    for (int s = 128; s > 0; s >>= 1) {
        if (t < s) red[t] = fmaxf(red[t], red[t + s]);
        __syncthreads();
    }
    m = red[0]; __syncthreads();
    float sum = 0.f;
    #pragma unroll
    for (int i = 0; i < 4; i++) { v[i] = __expf(v[i] - m); sum += v[i]; }
    red[t] = sum; __syncthreads();
    for (int s = 128; s > 0; s >>= 1) {
        if (t < s) red[t] += red[t + s];
        __syncthreads();
    }
    float inv = 1.0f / red[0];
    #pragma unroll
    for (int i = 0; i < 4; i++) row[t + i * 256] = v[i] * inv;
}

// ---------------- x = LayerNorm(x + r) * g + b ------------------------------
__global__ void add_ln(float* __restrict__ x, const float* __restrict__ r,
                       const float* __restrict__ g, const float* __restrict__ bb) {
    float* row = x + (size_t)blockIdx.x * D_;
    const float* rr = r + (size_t)blockIdx.x * D_;
    __shared__ float red[256];
    __shared__ float red2[256];
    int t = threadIdx.x;
    float v[4];
    float s = 0.f, s2 = 0.f;
    #pragma unroll
    for (int i = 0; i < 4; i++) {
        v[i] = row[t + i * 256] + rr[t + i * 256];
        s += v[i]; s2 += v[i] * v[i];
    }
    red[t] = s; red2[t] = s2; __syncthreads();
    for (int st = 128; st > 0; st >>= 1) {
        if (t < st) { red[t] += red[t + st]; red2[t] += red2[t + st]; }
        __syncthreads();
    }
    float mu = red[0] * (1.0f / D_);
    float var = red2[0] * (1.0f / D_) - mu * mu;
    float inv = rsqrtf(var + 1e-6f);
    #pragma unroll
    for (int i = 0; i < 4; i++) {
        int c = t + i * 256;
        row[c] = (v[i] - mu) * inv * g[c] + bb[c];
    }
}

__global__ void copyk(float* __restrict__ dst, const float* __restrict__ src, int n) {
    int i = blockIdx.x * 256 + threadIdx.x;
    if (i < n) dst[i] = src[i];
}

// ---------------------------------------------------------------------------
extern "C" void kernel_launch(void* const* d_in, const int* in_sizes, int n_in,
                              void* d_out, int out_size) {
    const float* x_in      = (const float*)d_in[0];
    const int*   mask      = (const int*)d_in[1];
    const float* attn_bias = (const float*)d_in[2];
    const float* Wq        = (const float*)d_in[3];
    const float* Wk        = (const float*)d_in[4];
    const float* Wv        = (const float*)d_in[5];
    const float* ln1_g     = (const float*)d_in[6];
    const float* ln1_b     = (const float*)d_in[7];
    const float* W1        = (const float*)d_in[8];
    const float* b1        = (const float*)d_in[9];
    const float* W2        = (const float*)d_in[10];
    const float* b2        = (const float*)d_in[11];
    const float* ln2_g     = (const float*)d_in[12];
    const float* ln2_b     = (const float*)d_in[13];
    float* out = (float*)d_out;

    float *px, *pq, *pk, *pv, *po, *ph, *pf;
    cudaGetSymbolAddress((void**)&px, g_x);
    cudaGetSymbolAddress((void**)&pq, g_q);
    cudaGetSymbolAddress((void**)&pk, g_k);
    cudaGetSymbolAddress((void**)&pv, g_v);
    cudaGetSymbolAddress((void**)&po, g_o);
    cudaGetSymbolAddress((void**)&ph, g_h);
    cudaGetSymbolAddress((void**)&pf, g_f);

    const int nX = BS_ * D_;
    copyk<<<(nX + 255) / 256, 256>>>(px, x_in, nX);

    dim3 gQKV(D_ / 128, BS_ / 128);        // 8 x 16
    dim3 gFF1(DFF_ / 128, BS_ / 128);      // 16 x 16
    dim3 gFF2(D_ / 128, BS_ / 128);        // 8 x 16
    dim3 gSc(S_ / 128, S_ / 128, B_ * H_); // 8 x 8 x 32
    dim3 gPV(1, S_ / 128, B_ * H_);        // 1 x 8 x 32

    for (int n = 0; n < L_; n++) {
        const float* wq = Wq + (size_t)n * D_ * D_;
        const float* wk = Wk + (size_t)n * D_ * D_;
        const float* wv = Wv + (size_t)n * D_ * D_;
        float* scores = out + (size_t)n * B_ * H_ * S_ * S_;

        gemm_tc<0><<<gQKV, 256>>>(px, wq, nullptr, pq, D_, D_);
        gemm_tc<0><<<gQKV, 256>>>(px, wk, nullptr, pk, D_, D_);
        gemm_tc<0><<<gQKV, 256>>>(px, wv, nullptr, pv, D_, D_);

        score_tc<<<gSc, 256>>>(attn_bias, mask, scores);
        softmax_rows<<<B_ * H_ * S_, 256>>>(scores);
        pv_tc<<<gPV, 256>>>(scores);

        add_ln<<<BS_, 256>>>(px, po, ln1_g + n * D_, ln1_b + n * D_);

        gemm_tc<2><<<gFF1, 256>>>(px, W1 + (size_t)n * D_ * DFF_, b1 + n * DFF_, ph, DFF_, D_);
        gemm_tc<1><<<gFF2, 256>>>(ph, W2 + (size_t)n * DFF_ * D_, b2 + n * D_, pf, D_, DFF_);

        add_ln<<<BS_, 256>>>(px, pf, ln2_g + n * D_, ln2_b + n * D_);
    }

    copyk<<<(nX + 255) / 256, 256>>>(out + (size_t)L_ * B_ * H_ * S_ * S_, px, nX);
}

// round 3
// speedup vs baseline: 4.1925x; 1.2204x over previous
#include <cuda_runtime.h>
#include <stdint.h>
#include <math.h>

#define B_   2
#define S_   1024
#define D_   1024
#define H_   16
#define DK_  64
#define DFF_ 2048
#define L_   4
#define BS_  (B_*S_)

// ---------------- scratch ----------------------------------------------------
__device__ float g_x[BS_*D_];
__device__ float g_q[BS_*D_];
__device__ float g_k[BS_*D_];
__device__ float g_v[BS_*D_];
__device__ float g_o[BS_*D_];
__device__ float g_h[BS_*DFF_];
__device__ float g_f[BS_*D_];

__device__ __forceinline__ float gelu_tanh_f(float x) {
    float x3 = x * x * x;
    return 0.5f * x * (1.0f + tanhf(0.7978845608028654f * (x + 0.044715f * x3)));
}

__device__ __forceinline__ uint32_t f2tf(float f) {
    uint32_t u;
    asm("cvt.rna.tf32.f32 %0, %1;" : "=r"(u) : "f"(f));
    return u;
}

__device__ __forceinline__ void mma_tf32(float* c, const uint32_t* a, const uint32_t* b) {
    asm volatile(
        "mma.sync.aligned.m16n8k8.row.col.f32.tf32.tf32.f32 "
        "{%0,%1,%2,%3}, {%4,%5,%6,%7}, {%8,%9}, {%0,%1,%2,%3};"
        : "+f"(c[0]), "+f"(c[1]), "+f"(c[2]), "+f"(c[3])
        : "r"(a[0]), "r"(a[1]), "r"(a[2]), "r"(a[3]), "r"(b[0]), "r"(b[1]));
}

__device__ __forceinline__ void cpa16(uint32_t saddr, const void* gptr) {
    asm volatile("cp.async.cg.shared.global [%0], [%1], 16;" :: "r"(saddr), "l"(gptr));
}
#define CP_COMMIT()  asm volatile("cp.async.commit_group;")
#define CP_WAIT(n)   asm volatile("cp.async.wait_group %0;" :: "n"(n))

// =============================================================================
// Pipelined GEMM: C[M,N] = A[M,K] @ W[K,N]. 128x128 tile, BK=32, 3-stage cp.async.
// 8 warps (2Mx4N), warp 64x32. EPI: 0 none, 1 +bias, 2 gelu(+bias).
// z = blockIdx.z selects (W, C) among up to 3 (fused QKV).
// smem: As[3][128][36] f32 ([m][k]), Bs[3][32][132] f32 ([k][n]).
// =============================================================================
#define GA_STRIDE 36
#define GB_STRIDE 132
#define GA_ELEMS  (128*GA_STRIDE)
#define GB_ELEMS  (32*GB_STRIDE)
#define GEMM_SMEM ((3*GA_ELEMS + 3*GB_ELEMS)*4)

template<int EPI>
__global__ __launch_bounds__(256)
void gemm_pipe(const float* __restrict__ A,
               const float* __restrict__ W0, const float* __restrict__ W1,
               const float* __restrict__ W2, const float* __restrict__ bias,
               float* __restrict__ C0, float* __restrict__ C1, float* __restrict__ C2,
               int N, int K) {
    extern __shared__ float smem[];
    float* AsBase = smem;
    float* BsBase = smem + 3*GA_ELEMS;

    const float* W = (blockIdx.z == 0) ? W0 : (blockIdx.z == 1) ? W1 : W2;
    float*       C = (blockIdx.z == 0) ? C0 : (blockIdx.z == 1) ? C1 : C2;

    const int tid = threadIdx.x;
    const int row0 = blockIdx.y * 128, col0 = blockIdx.x * 128;
    const int w = tid >> 5, lane = tid & 31;
    const int wm = w >> 2, wn = w & 3;
    const int grp = lane >> 2, qd = lane & 3;
    const int nIter = K >> 5;

    // load indices
    const int la_row = tid >> 1;              // A: 1024 chunks = 128 rows x 8; 4/thread
    const int lb_row = tid >> 5;              // B: 32 rows x 32 chunks; 4/thread

    uint32_t sA0 = (uint32_t)__cvta_generic_to_shared(AsBase);
    uint32_t sB0 = (uint32_t)__cvta_generic_to_shared(BsBase);

    #define LOAD_TILE(it, st) {                                                     \
        uint32_t sa = sA0 + (st)*GA_ELEMS*4;                                        \
        uint32_t sb = sB0 + (st)*GB_ELEMS*4;                                        \
        int kt = (it) << 5;                                                         \
        _Pragma("unroll")                                                           \
        for (int i = 0; i < 4; i++) {                                               \
            int idx = tid + i * 256;                                                \
            int r = idx >> 3, c16 = idx & 7;                                        \
            cpa16(sa + (r*GA_STRIDE + c16*4)*4,                                     \
                  &A[(size_t)(row0 + r) * K + kt + c16*4]);                         \
        }                                                                           \
        _Pragma("unroll")                                                           \
        for (int i = 0; i < 4; i++) {                                               \
            int idx = tid + i * 256;                                                \
            int r = idx >> 5, c4 = (idx & 31) * 4;                                  \
            cpa16(sb + (r*GB_STRIDE + c4)*4,                                        \
                  &W[(size_t)(kt + r) * N + col0 + c4]);                            \
        }                                                                           \
    }

    float acc[4][4][4] = {};

    LOAD_TILE(0, 0); CP_COMMIT();
    LOAD_TILE(1, 1); CP_COMMIT();

    for (int it = 0; it < nIter; it++) {
        CP_WAIT(1);
        __syncthreads();
        if (it + 2 < nIter) { LOAD_TILE(it + 2, (it + 2) % 3); }
        CP_COMMIT();

        const float* As = AsBase + (it % 3) * GA_ELEMS;
        const float* Bs = BsBase + (it % 3) * GB_ELEMS;
        #pragma unroll
        for (int kk = 0; kk < 4; kk++) {
            int kb = kk * 8;
            uint32_t af[4][4], bf[4][2];
            #pragma unroll
            for (int mf = 0; mf < 4; mf++) {
                int r = wm * 64 + mf * 16 + grp;
                af[mf][0] = f2tf(As[r * GA_STRIDE + kb + qd]);
                af[mf][1] = f2tf(As[(r + 8) * GA_STRIDE + kb + qd]);
                af[mf][2] = f2tf(As[r * GA_STRIDE + kb + qd + 4]);
                af[mf][3] = f2tf(As[(r + 8) * GA_STRIDE + kb + qd + 4]);
            }
            #pragma unroll
            for (int nf = 0; nf < 4; nf++) {
                int c = wn * 32 + nf * 8 + grp;
                bf[nf][0] = f2tf(Bs[(kb + qd) * GB_STRIDE + c]);
                bf[nf][1] = f2tf(Bs[(kb + qd + 4) * GB_STRIDE + c]);
            }
            #pragma unroll
            for (int mf = 0; mf < 4; mf++)
                #pragma unroll
                for (int nf = 0; nf < 4; nf++)
                    mma_tf32(acc[mf][nf], af[mf], bf[nf]);
        }
        __syncthreads();
    }
    #undef LOAD_TILE

    #pragma unroll
    for (int mf = 0; mf < 4; mf++) {
        int r = row0 + wm * 64 + mf * 16 + grp;
        #pragma unroll
        for (int nf = 0; nf < 4; nf++) {
            int c = col0 + wn * 32 + nf * 8 + 2 * qd;
            float* a = acc[mf][nf];
            float v0 = a[0], v1 = a[1], v2 = a[2], v3 = a[3];
            if (EPI >= 1) {
                float b0 = bias[c], b1 = bias[c + 1];
                v0 += b0; v1 += b1; v2 += b0; v3 += b1;
            }
            if (EPI == 2) {
                v0 = gelu_tanh_f(v0); v1 = gelu_tanh_f(v1);
                v2 = gelu_tanh_f(v2); v3 = gelu_tanh_f(v3);
            }
            C[(size_t)r * N + c] = v0;       C[(size_t)r * N + c + 1] = v1;
            C[(size_t)(r + 8) * N + c] = v2; C[(size_t)(r + 8) * N + c + 1] = v3;
        }
    }
}

// =============================================================================
// Scores: per z=(b,h): S = scale*Q K^T + bias, masked. 128x128 tile, K=64 one shot.
// smem: Qs[128][68] ([m][k]), Ks[128][68] ([n][k]).
// =============================================================================
#define SC_STRIDE 68
#define SC_ELEMS  (128*SC_STRIDE)
#define SC_SMEM   (2*SC_ELEMS*4)

__global__ __launch_bounds__(256)
void score_tc(const float* __restrict__ attn_bias, const int* __restrict__ mask,
              float* __restrict__ out) {
    extern __shared__ float smem[];
    float* Qs = smem;
    float* Ks = smem + SC_ELEMS;

    const int tid = threadIdx.x;
    const int row0 = blockIdx.y * 128, col0 = blockIdx.x * 128;
    const int z = blockIdx.z, b = z >> 4, h = z & 15;
    const int w = tid >> 5, lane = tid & 31;
    const int wm = w >> 2, wn = w & 3;
    const int grp = lane >> 2, qd = lane & 3;

    const float* Q = g_q + (size_t)b * S_ * D_ + h * DK_;
    const float* Kp = g_k + (size_t)b * S_ * D_ + h * DK_;

    uint32_t sQ = (uint32_t)__cvta_generic_to_shared(Qs);
    uint32_t sK = (uint32_t)__cvta_generic_to_shared(Ks);
    #pragma unroll
    for (int i = 0; i < 8; i++) {
        int idx = tid + i * 256;
        int r = idx >> 4, c16 = idx & 15;
        cpa16(sQ + (r*SC_STRIDE + c16*4)*4, &Q[(size_t)(row0 + r) * D_ + c16*4]);
    }
    #pragma unroll
    for (int i = 0; i < 8; i++) {
        int idx = tid + i * 256;
        int r = idx >> 4, c16 = idx & 15;
        cpa16(sK + (r*SC_STRIDE + c16*4)*4, &Kp[(size_t)(col0 + r) * D_ + c16*4]);
    }
    CP_COMMIT();
    CP_WAIT(0);
    __syncthreads();

    float acc[4][4][4] = {};
    #pragma unroll
    for (int kk = 0; kk < 8; kk++) {
        int kb = kk * 8;
        uint32_t af[4][4], bf[4][2];
        #pragma unroll
        for (int mf = 0; mf < 4; mf++) {
            int r = wm * 64 + mf * 16 + grp;
            af[mf][0] = f2tf(Qs[r * SC_STRIDE + kb + qd]);
            af[mf][1] = f2tf(Qs[(r + 8) * SC_STRIDE + kb + qd]);
            af[mf][2] = f2tf(Qs[r * SC_STRIDE + kb + qd + 4]);
            af[mf][3] = f2tf(Qs[(r + 8) * SC_STRIDE + kb + qd + 4]);
        }
        #pragma unroll
        for (int nf = 0; nf < 4; nf++) {
            int c = wn * 32 + nf * 8 + grp;
            bf[nf][0] = f2tf(Ks[c * SC_STRIDE + kb + qd]);
            bf[nf][1] = f2tf(Ks[c * SC_STRIDE + kb + qd + 4]);
        }
        #pragma unroll
        for (int mf = 0; mf < 4; mf++)
            #pragma unroll
            for (int nf = 0; nf < 4; nf++)
                mma_tf32(acc[mf][nf], af[mf], bf[nf]);
    }

    const float scale = 0.125f;
    const float* biasM = attn_bias + (size_t)z * S_ * S_;
    float* Cm = out + (size_t)z * S_ * S_;
    #pragma unroll
    for (int mf = 0; mf < 4; mf++) {
        int r = row0 + wm * 64 + mf * 16 + grp;
        #pragma unroll
        for (int nf = 0; nf < 4; nf++) {
            int c = col0 + wn * 32 + nf * 8 + 2 * qd;
            float* a = acc[mf][nf];
            int mk0 = mask[b * S_ + c], mk1 = mask[b * S_ + c + 1];
            float o00 = mk0 ? a[0] * scale + biasM[(size_t)r * S_ + c]       : -9e15f;
            float o01 = mk1 ? a[1] * scale + biasM[(size_t)r * S_ + c + 1]   : -9e15f;
            float o10 = mk0 ? a[2] * scale + biasM[(size_t)(r+8) * S_ + c]   : -9e15f;
            float o11 = mk1 ? a[3] * scale + biasM[(size_t)(r+8) * S_ + c+1] : -9e15f;
            Cm[(size_t)r * S_ + c] = o00;       Cm[(size_t)r * S_ + c + 1] = o01;
            Cm[(size_t)(r + 8) * S_ + c] = o10; Cm[(size_t)(r + 8) * S_ + c + 1] = o11;
        }
    }
}

// =============================================================================
// PV: per z: O_slice[S,64] = P[S,S] @ V_slice[S,64]. 128x64 tile, BK=32, 3-stage.
// 8 warps (4Mx2N), warp 32x32. smem: As[3][128][36], Bs[3][32][68].
// =============================================================================
#define PB_STRIDE 68
#define PB_ELEMS  (32*PB_STRIDE)
#define PV_SMEM   ((3*GA_ELEMS + 3*PB_ELEMS)*4)

__global__ __launch_bounds__(256)
void pv_pipe(const float* __restrict__ p) {
    extern __shared__ float smem[];
    float* AsBase = smem;
    float* BsBase = smem + 3*GA_ELEMS;

    const int tid = threadIdx.x;
    const int row0 = blockIdx.y * 128;
    const int z = blockIdx.z, b = z >> 4, h = z & 15;
    const int w = tid >> 5, lane = tid & 31;
    const int wm = w >> 1, wn = w & 1;
    const int grp = lane >> 2, qd = lane & 3;

    const float* A = p + (size_t)z * S_ * S_;
    const float* V = g_v + (size_t)b * S_ * D_ + h * DK_;

    uint32_t sA0 = (uint32_t)__cvta_generic_to_shared(AsBase);
    uint32_t sB0 = (uint32_t)__cvta_generic_to_shared(BsBase);

    #define LOAD_TILE(it, st) {                                                     \
        uint32_t sa = sA0 + (st)*GA_ELEMS*4;                                        \
        uint32_t sb = sB0 + (st)*PB_ELEMS*4;                                        \
        int kt = (it) << 5;                                                         \
        _Pragma("unroll")                                                           \
        for (int i = 0; i < 4; i++) {                                               \
            int idx = tid + i * 256;                                                \
            int r = idx >> 3, c16 = idx & 7;                                        \
            cpa16(sa + (r*GA_STRIDE + c16*4)*4,                                     \
                  &A[(size_t)(row0 + r) * S_ + kt + c16*4]);                        \
        }                                                                           \
        _Pragma("unroll")                                                           \
        for (int i = 0; i < 2; i++) {                                               \
            int idx = tid + i * 256;                                                \
            int r = idx >> 4, c4 = (idx & 15) * 4;                                  \
            cpa16(sb + (r*PB_STRIDE + c4)*4,                                        \
                  &V[(size_t)(kt + r) * D_ + c4]);                                  \
        }                                                                           \
    }

    float acc[2][4][4] = {};
    const int nIter = S_ >> 5;

    LOAD_TILE(0, 0); CP_COMMIT();
    LOAD_TILE(1, 1); CP_COMMIT();

    for (int it = 0; it < nIter; it++) {
        CP_WAIT(1);
        __syncthreads();
        if (it + 2 < nIter) { LOAD_TILE(it + 2, (it + 2) % 3); }
        CP_COMMIT();

        const float* As = AsBase + (it % 3) * GA_ELEMS;
        const float* Bs = BsBase + (it % 3) * PB_ELEMS;
        #pragma unroll
        for (int kk = 0; kk < 4; kk++) {
            int kb = kk * 8;
            uint32_t af[2][4], bf[4][2];
            #pragma unroll
            for (int mf = 0; mf < 2; mf++) {
                int r = wm * 32 + mf * 16 + grp;
                af[mf][0] = f2tf(As[r * GA_STRIDE + kb + qd]);
                af[mf][1] = f2tf(As[(r + 8) * GA_STRIDE + kb + qd]);
                af[mf][2] = f2tf(As[r * GA_STRIDE + kb + qd + 4]);
                af[mf][3] = f2tf(As[(r + 8) * GA_STRIDE + kb + qd + 4]);
            }
            #pragma unroll
            for (int nf = 0; nf < 4; nf++) {
                int c = wn * 32 + nf * 8 + grp;
                bf[nf][0] = f2tf(Bs[(kb + qd) * PB_STRIDE + c]);
                bf[nf][1] = f2tf(Bs[(kb + qd + 4) * PB_STRIDE + c]);
            }
            #pragma unroll
            for (int mf = 0; mf < 2; mf++)
                #pragma unroll
                for (int nf = 0; nf < 4; nf++)
                    mma_tf32(acc[mf][nf], af[mf], bf[nf]);
        }
        __syncthreads();
    }
    #undef LOAD_TILE

    float* O = g_o + (size_t)b * S_ * D_ + h * DK_;
    #pragma unroll
    for (int mf = 0; mf < 2; mf++) {
        int r = row0 + wm * 32 + mf * 16 + grp;
        #pragma unroll
        for (int nf = 0; nf < 4; nf++) {
            int c = wn * 32 + nf * 8 + 2 * qd;
            float* a = acc[mf][nf];
            O[(size_t)r * D_ + c] = a[0];       O[(size_t)r * D_ + c + 1] = a[1];
            O[(size_t)(r + 8) * D_ + c] = a[2]; O[(size_t)(r + 8) * D_ + c + 1] = a[3];
        }
    }
}

// ---------------- row softmax over S=1024, in place -------------------------
__global__ void softmax_rows(float* __restrict__ p) {
    float* row = p + (size_t)blockIdx.x * S_;
    __shared__ float red[256];
    int t = threadIdx.x;
    float v[4];
    float m = -INFINITY;
    #pragma unroll
    for (int i = 0; i < 4; i++) { v[i] = row[t + i * 256]; m = fmaxf(m, v[i]); }
    red[t] = m; __syncthreads();
    for (int s = 128; s > 0; s >>= 1) {
        if (t < s) red[t] = fmaxf(red[t], red[t + s]);
        __syncthreads();
    }
    m = red[0]; __syncthreads();
    float sum = 0.f;
    #pragma unroll
    for (int i = 0; i < 4; i++) { v[i] = __expf(v[i] - m); sum += v[i]; }
    red[t] = sum; __syncthreads();
    for (int s = 128; s > 0; s >>= 1) {
        if (t < s) red[t] += red[t + s];
        __syncthreads();
    }
    float inv = 1.0f / red[0];
    #pragma unroll
    for (int i = 0; i < 4; i++) row[t + i * 256] = v[i] * inv;
}

// ---------------- x = LayerNorm(x + r) * g + b ------------------------------
__global__ void add_ln(float* __restrict__ x, const float* __restrict__ r,
                       const float* __restrict__ g, const float* __restrict__ bb) {
    float* row = x + (size_t)blockIdx.x * D_;
    const float* rr = r + (size_t)blockIdx.x * D_;
    __shared__ float red[256];
    __shared__ float red2[256];
    int t = threadIdx.x;
    float v[4];
    float s = 0.f, s2 = 0.f;
    #pragma unroll
    for (int i = 0; i < 4; i++) {
        v[i] = row[t + i * 256] + rr[t + i * 256];
        s += v[i]; s2 += v[i] * v[i];
    }
    red[t] = s; red2[t] = s2; __syncthreads();
    for (int st = 128; st > 0; st >>= 1) {
        if (t < st) { red[t] += red[t + st]; red2[t] += red2[t + st]; }
        __syncthreads();
    }
    float mu = red[0] * (1.0f / D_);
    float var = red2[0] * (1.0f / D_) - mu * mu;
    float inv = rsqrtf(var + 1e-6f);
    #pragma unroll
    for (int i = 0; i < 4; i++) {
        int c = t + i * 256;
        row[c] = (v[i] - mu) * inv * g[c] + bb[c];
    }
}

__global__ void copyk(float* __restrict__ dst, const float* __restrict__ src, int n) {
    int i = blockIdx.x * 256 + threadIdx.x;
    if (i < n) dst[i] = src[i];
}

// ---------------------------------------------------------------------------
extern "C" void kernel_launch(void* const* d_in, const int* in_sizes, int n_in,
                              void* d_out, int out_size) {
    const float* x_in      = (const float*)d_in[0];
    const int*   mask      = (const int*)d_in[1];
    const float* attn_bias = (const float*)d_in[2];
    const float* Wq        = (const float*)d_in[3];
    const float* Wk        = (const float*)d_in[4];
    const float* Wv        = (const float*)d_in[5];
    const float* ln1_g     = (const float*)d_in[6];
    const float* ln1_b     = (const float*)d_in[7];
    const float* W1        = (const float*)d_in[8];
    const float* b1        = (const float*)d_in[9];
    const float* W2        = (const float*)d_in[10];
    const float* b2        = (const float*)d_in[11];
    const float* ln2_g     = (const float*)d_in[12];
    const float* ln2_b     = (const float*)d_in[13];
    float* out = (float*)d_out;

    cudaFuncSetAttribute(gemm_pipe<0>, cudaFuncAttributeMaxDynamicSharedMemorySize, GEMM_SMEM);
    cudaFuncSetAttribute(gemm_pipe<1>, cudaFuncAttributeMaxDynamicSharedMemorySize, GEMM_SMEM);
    cudaFuncSetAttribute(gemm_pipe<2>, cudaFuncAttributeMaxDynamicSharedMemorySize, GEMM_SMEM);
    cudaFuncSetAttribute(score_tc,     cudaFuncAttributeMaxDynamicSharedMemorySize, SC_SMEM);
    cudaFuncSetAttribute(pv_pipe,      cudaFuncAttributeMaxDynamicSharedMemorySize, PV_SMEM);

    float *px, *pq, *pk, *pv, *po, *ph, *pf;
    cudaGetSymbolAddress((void**)&px, g_x);
    cudaGetSymbolAddress((void**)&pq, g_q);
    cudaGetSymbolAddress((void**)&pk, g_k);
    cudaGetSymbolAddress((void**)&pv, g_v);
    cudaGetSymbolAddress((void**)&po, g_o);
    cudaGetSymbolAddress((void**)&ph, g_h);
    cudaGetSymbolAddress((void**)&pf, g_f);

    const int nX = BS_ * D_;
    copyk<<<(nX + 255) / 256, 256>>>(px, x_in, nX);

    dim3 gQKV(D_ / 128, BS_ / 128, 3);     // 8 x 16 x 3 = 384 blocks
    dim3 gFF1(DFF_ / 128, BS_ / 128, 1);   // 16 x 16
    dim3 gFF2(D_ / 128, BS_ / 128, 1);     // 8 x 16
    dim3 gSc(S_ / 128, S_ / 128, B_ * H_); // 8 x 8 x 32
    dim3 gPV(1, S_ / 128, B_ * H_);        // 1 x 8 x 32

    for (int n = 0; n < L_; n++) {
        const float* wq = Wq + (size_t)n * D_ * D_;
        const float* wk = Wk + (size_t)n * D_ * D_;
        const float* wv = Wv + (size_t)n * D_ * D_;
        float* scores = out + (size_t)n * B_ * H_ * S_ * S_;

        gemm_pipe<0><<<gQKV, 256, GEMM_SMEM>>>(px, wq, wk, wv, nullptr,
                                               pq, pk, pv, D_, D_);

        score_tc<<<gSc, 256, SC_SMEM>>>(attn_bias, mask, scores);
        softmax_rows<<<B_ * H_ * S_, 256>>>(scores);
        pv_pipe<<<gPV, 256, PV_SMEM>>>(scores);

        add_ln<<<BS_, 256>>>(px, po, ln1_g + n * D_, ln1_b + n * D_);

        const float* w1 = W1 + (size_t)n * D_ * DFF_;
        const float* w2 = W2 + (size_t)n * DFF_ * D_;
        gemm_pipe<2><<<gFF1, 256, GEMM_SMEM>>>(px, w1, w1, w1, b1 + n * DFF_,
                                               ph, ph, ph, DFF_, D_);
        gemm_pipe<1><<<gFF2, 256, GEMM_SMEM>>>(ph, w2, w2, w2, b2 + n * D_,
                                               pf, pf, pf, D_, DFF_);

        add_ln<<<BS_, 256>>>(px, pf, ln2_g + n * D_, ln2_b + n * D_);
    }

    copyk<<<(nX + 255) / 256, 256>>>(out + (size_t)L_ * B_ * H_ * S_ * S_, px, nX);
}

// round 4
// speedup vs baseline: 4.4731x; 1.0669x over previous
#include <cuda_runtime.h>
#include <stdint.h>
#include <math.h>

#define B_   2
#define S_   1024
#define D_   1024
#define H_   16
#define DK_  64
#define DFF_ 2048
#define L_   4
#define BS_  (B_*S_)

// ---------------- scratch ----------------------------------------------------
__device__ float g_x[BS_*D_];
__device__ float g_q[BS_*D_];
__device__ float g_k[BS_*D_];
__device__ float g_v[BS_*D_];
__device__ float g_o[BS_*D_];
__device__ float g_h[BS_*DFF_];
__device__ float g_f[BS_*D_];

__device__ __forceinline__ float gelu_tanh_f(float x) {
    float x3 = x * x * x;
    return 0.5f * x * (1.0f + tanhf(0.7978845608028654f * (x + 0.044715f * x3)));
}

__device__ __forceinline__ uint32_t f2tf(float f) {
    uint32_t u;
    asm("cvt.rna.tf32.f32 %0, %1;" : "=r"(u) : "f"(f));
    return u;
}

__device__ __forceinline__ void mma_tf32(float* c, const uint32_t* a, const uint32_t* b) {
    asm volatile(
        "mma.sync.aligned.m16n8k8.row.col.f32.tf32.tf32.f32 "
        "{%0,%1,%2,%3}, {%4,%5,%6,%7}, {%8,%9}, {%0,%1,%2,%3};"
        : "+f"(c[0]), "+f"(c[1]), "+f"(c[2]), "+f"(c[3])
        : "r"(a[0]), "r"(a[1]), "r"(a[2]), "r"(a[3]), "r"(b[0]), "r"(b[1]));
}

__device__ __forceinline__ void cpa16(uint32_t saddr, const void* gptr) {
    asm volatile("cp.async.cg.shared.global [%0], [%1], 16;" :: "r"(saddr), "l"(gptr));
}
#define CP_COMMIT()  asm volatile("cp.async.commit_group;")
#define CP_WAIT(n)   asm volatile("cp.async.wait_group %0;" :: "n"(n))

// =============================================================================
// Pipelined GEMM: C[M,N] = A[M,K] @ W[K,N]. 128x128 tile, BK=32, 3-stage cp.async.
// 8 warps (2Mx4N). EPI: 0 none, 1 +bias, 2 gelu(+bias). z selects fused QKV.
// =============================================================================
#define GA_STRIDE 36
#define GB_STRIDE 132
#define GA_ELEMS  (128*GA_STRIDE)
#define GB_ELEMS  (32*GB_STRIDE)
#define GEMM_SMEM ((3*GA_ELEMS + 3*GB_ELEMS)*4)

template<int EPI>
__global__ __launch_bounds__(256)
void gemm_pipe(const float* __restrict__ A,
               const float* __restrict__ W0, const float* __restrict__ W1,
               const float* __restrict__ W2, const float* __restrict__ bias,
               float* __restrict__ C0, float* __restrict__ C1, float* __restrict__ C2,
               int N, int K) {
    extern __shared__ float smem[];
    float* AsBase = smem;
    float* BsBase = smem + 3*GA_ELEMS;

    const float* W = (blockIdx.z == 0) ? W0 : (blockIdx.z == 1) ? W1 : W2;
    float*       C = (blockIdx.z == 0) ? C0 : (blockIdx.z == 1) ? C1 : C2;

    const int tid = threadIdx.x;
    const int row0 = blockIdx.y * 128, col0 = blockIdx.x * 128;
    const int w = tid >> 5, lane = tid & 31;
    const int wm = w >> 2, wn = w & 3;
    const int grp = lane >> 2, qd = lane & 3;
    const int nIter = K >> 5;

    uint32_t sA0 = (uint32_t)__cvta_generic_to_shared(AsBase);
    uint32_t sB0 = (uint32_t)__cvta_generic_to_shared(BsBase);

    #define LOAD_TILE(it, st) {                                                     \
        uint32_t sa = sA0 + (st)*GA_ELEMS*4;                                        \
        uint32_t sb = sB0 + (st)*GB_ELEMS*4;                                        \
        int kt = (it) << 5;                                                         \
        _Pragma("unroll")                                                           \
        for (int i = 0; i < 4; i++) {                                               \
            int idx = tid + i * 256;                                                \
            int r = idx >> 3, c16 = idx & 7;                                        \
            cpa16(sa + (r*GA_STRIDE + c16*4)*4,                                     \
                  &A[(size_t)(row0 + r) * K + kt + c16*4]);                         \
        }                                                                           \
        _Pragma("unroll")                                                           \
        for (int i = 0; i < 4; i++) {                                               \
            int idx = tid + i * 256;                                                \
            int r = idx >> 5, c4 = (idx & 31) * 4;                                  \
            cpa16(sb + (r*GB_STRIDE + c4)*4,                                        \
                  &W[(size_t)(kt + r) * N + col0 + c4]);                            \
        }                                                                           \
    }

    float acc[4][4][4] = {};

    LOAD_TILE(0, 0); CP_COMMIT();
    LOAD_TILE(1, 1); CP_COMMIT();

    for (int it = 0; it < nIter; it++) {
        CP_WAIT(1);
        __syncthreads();
        if (it + 2 < nIter) { LOAD_TILE(it + 2, (it + 2) % 3); }
        CP_COMMIT();

        const float* As = AsBase + (it % 3) * GA_ELEMS;
        const float* Bs = BsBase + (it % 3) * GB_ELEMS;
        #pragma unroll
        for (int kk = 0; kk < 4; kk++) {
            int kb = kk * 8;
            uint32_t af[4][4], bf[4][2];
            #pragma unroll
            for (int mf = 0; mf < 4; mf++) {
                int r = wm * 64 + mf * 16 + grp;
                af[mf][0] = f2tf(As[r * GA_STRIDE + kb + qd]);
                af[mf][1] = f2tf(As[(r + 8) * GA_STRIDE + kb + qd]);
                af[mf][2] = f2tf(As[r * GA_STRIDE + kb + qd + 4]);
                af[mf][3] = f2tf(As[(r + 8) * GA_STRIDE + kb + qd + 4]);
            }
            #pragma unroll
            for (int nf = 0; nf < 4; nf++) {
                int c = wn * 32 + nf * 8 + grp;
                bf[nf][0] = f2tf(Bs[(kb + qd) * GB_STRIDE + c]);
                bf[nf][1] = f2tf(Bs[(kb + qd + 4) * GB_STRIDE + c]);
            }
            #pragma unroll
            for (int mf = 0; mf < 4; mf++)
                #pragma unroll
                for (int nf = 0; nf < 4; nf++)
                    mma_tf32(acc[mf][nf], af[mf], bf[nf]);
        }
        __syncthreads();
    }
    #undef LOAD_TILE

    #pragma unroll
    for (int mf = 0; mf < 4; mf++) {
        int r = row0 + wm * 64 + mf * 16 + grp;
        #pragma unroll
        for (int nf = 0; nf < 4; nf++) {
            int c = col0 + wn * 32 + nf * 8 + 2 * qd;
            float* a = acc[mf][nf];
            float v0 = a[0], v1 = a[1], v2 = a[2], v3 = a[3];
            if (EPI >= 1) {
                float b0 = bias[c], b1 = bias[c + 1];
                v0 += b0; v1 += b1; v2 += b0; v3 += b1;
            }
            if (EPI == 2) {
                v0 = gelu_tanh_f(v0); v1 = gelu_tanh_f(v1);
                v2 = gelu_tanh_f(v2); v3 = gelu_tanh_f(v3);
            }
            C[(size_t)r * N + c] = v0;       C[(size_t)r * N + c + 1] = v1;
            C[(size_t)(r + 8) * N + c] = v2; C[(size_t)(r + 8) * N + c + 1] = v3;
        }
    }
}

// =============================================================================
// Fused attention: per CTA = 32 query rows of one (b,h).
//   Phase 1: S[32,1024] = scale * Q Kᵀ   (K streamed, double-buffered)  -> smem
//   Phase 2: warp-per-row: + bias, mask, softmax; write p to gmem (only pass)
//   Phase 3: O[32,64] = P[32,1024] @ V   (V streamed, double-buffered)
// smem: sS[32][1028], Qs[32][68], KV[2][128][68]  = 209,920 B
// =============================================================================
#define FA_SSTRIDE 1028
#define FA_SBUF    (32*FA_SSTRIDE)      // 32896
#define FA_QOFF    FA_SBUF
#define FA_KVOFF   (FA_SBUF + 32*68)    // 35072
#define FA_KVBUF   (128*68)             // 8704
#define FA_SMEM    ((FA_KVOFF + 2*FA_KVBUF)*4)

__global__ __launch_bounds__(256)
void fused_attn(const float* __restrict__ attn_bias, const int* __restrict__ mask,
                float* __restrict__ out) {
    extern __shared__ float smem[];
    float* sS  = smem;
    float* Qs  = smem + FA_QOFF;
    float* KVb = smem + FA_KVOFF;

    const int tid = threadIdx.x;
    const int w = tid >> 5, lane = tid & 31;
    const int wm = w >> 2, wn = w & 3;
    const int grp = lane >> 2, qd = lane & 3;
    const int row0 = blockIdx.x * 32;
    const int z = blockIdx.y, b = z >> 4, h = z & 15;

    const float* Qg = g_q + (size_t)b*S_*D_ + h*DK_;
    const float* Kg = g_k + (size_t)b*S_*D_ + h*DK_;
    const float* Vg = g_v + (size_t)b*S_*D_ + h*DK_;

    uint32_t sQ  = (uint32_t)__cvta_generic_to_shared(Qs);
    uint32_t sKV = (uint32_t)__cvta_generic_to_shared(KVb);

    // preload Q (32x64) + K tile 0 (128x64) as one group
    #pragma unroll
    for (int i = 0; i < 2; i++) {
        int idx = tid + i*256;
        int r = idx >> 4, c = (idx & 15)*4;
        cpa16(sQ + (r*68 + c)*4, &Qg[(size_t)(row0+r)*D_ + c]);
    }
    #pragma unroll
    for (int i = 0; i < 8; i++) {
        int idx = tid + i*256;
        int r = idx >> 4, c = (idx & 15)*4;
        cpa16(sKV + (r*68 + c)*4, &Kg[(size_t)r*D_ + c]);
    }
    CP_COMMIT();

    // ---- phase 1: S = scale * Q K^T  (8 key tiles of 128) ----
    for (int t = 0; t < 8; t++) {
        __syncthreads();
        if (t + 1 < 8) {
            uint32_t dst = sKV + ((t+1)&1)*FA_KVBUF*4;
            int key0 = (t+1)*128;
            #pragma unroll
            for (int i = 0; i < 8; i++) {
                int idx = tid + i*256;
                int r = idx >> 4, c = (idx & 15)*4;
                cpa16(dst + (r*68 + c)*4, &Kg[(size_t)(key0+r)*D_ + c]);
            }
        }
        CP_COMMIT();
        CP_WAIT(1);
        __syncthreads();

        const float* Ks = KVb + (t&1)*FA_KVBUF;
        float acc[4][4] = {};
        #pragma unroll
        for (int kb8 = 0; kb8 < 8; kb8++) {
            int kb = kb8 * 8;
            uint32_t af[4], bf[4][2];
            int r = wm*16 + grp;
            af[0] = f2tf(Qs[r*68 + kb + qd]);
            af[1] = f2tf(Qs[(r+8)*68 + kb + qd]);
            af[2] = f2tf(Qs[r*68 + kb + qd + 4]);
            af[3] = f2tf(Qs[(r+8)*68 + kb + qd + 4]);
            #pragma unroll
            for (int nf = 0; nf < 4; nf++) {
                int c = wn*32 + nf*8 + grp;
                bf[nf][0] = f2tf(Ks[c*68 + kb + qd]);
                bf[nf][1] = f2tf(Ks[c*68 + kb + qd + 4]);
            }
            #pragma unroll
            for (int nf = 0; nf < 4; nf++)
                mma_tf32(acc[nf], af, bf[nf]);
        }
        {
            int r = wm*16 + grp;
            #pragma unroll
            for (int nf = 0; nf < 4; nf++) {
                int c = t*128 + wn*32 + nf*8 + 2*qd;
                sS[r*FA_SSTRIDE + c]       = acc[nf][0] * 0.125f;
                sS[r*FA_SSTRIDE + c + 1]   = acc[nf][1] * 0.125f;
                sS[(r+8)*FA_SSTRIDE + c]   = acc[nf][2] * 0.125f;
                sS[(r+8)*FA_SSTRIDE + c+1] = acc[nf][3] * 0.125f;
            }
        }
    }
    __syncthreads();

    // prefetch V tile 0 (overlaps softmax)
    #pragma unroll
    for (int i = 0; i < 8; i++) {
        int idx = tid + i*256;
        int r = idx >> 4, c = (idx & 15)*4;
        cpa16(sKV + (r*68 + c)*4, &Vg[(size_t)r*D_ + c]);
    }
    CP_COMMIT();

    // ---- phase 2: softmax, warp per row (4 rows/warp) ----
    {
        const float* biasZ = attn_bias + (size_t)z*S_*S_;
        float* outZ = out + (size_t)z*S_*S_;
        const int* maskB = mask + b*S_;
        #pragma unroll
        for (int ri = 0; ri < 4; ri++) {
            int r = w*4 + ri;
            const float* bRow = biasZ + (size_t)(row0+r)*S_;
            float* oRow = outZ + (size_t)(row0+r)*S_;
            float* sRow = sS + r*FA_SSTRIDE;
            float4 vals[8];
            float m = -INFINITY;
            #pragma unroll
            for (int j = 0; j < 8; j++) {
                int c = lane*4 + j*128;
                float4 sv = *(float4*)&sRow[c];
                float4 bv = *(const float4*)&bRow[c];
                int4 mk = *(const int4*)&maskB[c];
                float4 v;
                v.x = mk.x ? sv.x + bv.x : -9e15f;
                v.y = mk.y ? sv.y + bv.y : -9e15f;
                v.z = mk.z ? sv.z + bv.z : -9e15f;
                v.w = mk.w ? sv.w + bv.w : -9e15f;
                vals[j] = v;
                m = fmaxf(m, fmaxf(fmaxf(v.x, v.y), fmaxf(v.z, v.w)));
            }
            #pragma unroll
            for (int o = 16; o > 0; o >>= 1) m = fmaxf(m, __shfl_xor_sync(~0u, m, o));
            float sum = 0.f;
            #pragma unroll
            for (int j = 0; j < 8; j++) {
                float4 v = vals[j];
                v.x = __expf(v.x - m); v.y = __expf(v.y - m);
                v.z = __expf(v.z - m); v.w = __expf(v.w - m);
                vals[j] = v;
                sum += v.x + v.y + v.z + v.w;
            }
            #pragma unroll
            for (int o = 16; o > 0; o >>= 1) sum += __shfl_xor_sync(~0u, sum, o);
            float inv = 1.0f / sum;
            #pragma unroll
            for (int j = 0; j < 8; j++) {
                int c = lane*4 + j*128;
                float4 v = vals[j];
                v.x *= inv; v.y *= inv; v.z *= inv; v.w *= inv;
                *(float4*)&sRow[c] = v;
                *(float4*)&oRow[c] = v;
            }
        }
    }

    // ---- phase 3: O = P @ V  (8 value tiles of 128) ----
    float accO[2][4] = {};
    for (int t = 0; t < 8; t++) {
        __syncthreads();
        if (t + 1 < 8) {
            uint32_t dst = sKV + ((t+1)&1)*FA_KVBUF*4;
            int key0 = (t+1)*128;
            #pragma unroll
            for (int i = 0; i < 8; i++) {
                int idx = tid + i*256;
                int r = idx >> 4, c = (idx & 15)*4;
                cpa16(dst + (r*68 + c)*4, &Vg[(size_t)(key0+r)*D_ + c]);
            }
        }
        CP_COMMIT();
        CP_WAIT(1);
        __syncthreads();

        const float* Vs = KVb + (t&1)*FA_KVBUF;
        #pragma unroll
        for (int kb8 = 0; kb8 < 16; kb8++) {
            int kcol = t*128 + kb8*8;
            uint32_t af[4];
            int r = wm*16 + grp;
            af[0] = f2tf(sS[r*FA_SSTRIDE + kcol + qd]);
            af[1] = f2tf(sS[(r+8)*FA_SSTRIDE + kcol + qd]);
            af[2] = f2tf(sS[r*FA_SSTRIDE + kcol + qd + 4]);
            af[3] = f2tf(sS[(r+8)*FA_SSTRIDE + kcol + qd + 4]);
            #pragma unroll
            for (int nf = 0; nf < 2; nf++) {
                int c = wn*16 + nf*8 + grp;
                uint32_t bf[2];
                bf[0] = f2tf(Vs[(kb8*8 + qd)*68 + c]);
                bf[1] = f2tf(Vs[(kb8*8 + qd + 4)*68 + c]);
                mma_tf32(accO[nf], af, bf);
            }
        }
    }
    {
        float* Og = g_o + (size_t)b*S_*D_ + h*DK_;
        int r = row0 + wm*16 + grp;
        #pragma unroll
        for (int nf = 0; nf < 2; nf++) {
            int c = wn*16 + nf*8 + 2*qd;
            Og[(size_t)r*D_ + c]       = accO[nf][0];
            Og[(size_t)r*D_ + c + 1]   = accO[nf][1];
            Og[(size_t)(r+8)*D_ + c]   = accO[nf][2];
            Og[(size_t)(r+8)*D_ + c+1] = accO[nf][3];
        }
    }
}

// ---------------- x = LayerNorm(x + r) * g + b ------------------------------
__global__ void add_ln(float* __restrict__ x, const float* __restrict__ r,
                       const float* __restrict__ g, const float* __restrict__ bb) {
    float* row = x + (size_t)blockIdx.x * D_;
    const float* rr = r + (size_t)blockIdx.x * D_;
    __shared__ float red[256];
    __shared__ float red2[256];
    int t = threadIdx.x;
    float v[4];
    float s = 0.f, s2 = 0.f;
    #pragma unroll
    for (int i = 0; i < 4; i++) {
        v[i] = row[t + i * 256] + rr[t + i * 256];
        s += v[i]; s2 += v[i] * v[i];
    }
    red[t] = s; red2[t] = s2; __syncthreads();
    for (int st = 128; st > 0; st >>= 1) {
        if (t < st) { red[t] += red[t + st]; red2[t] += red2[t + st]; }
        __syncthreads();
    }
    float mu = red[0] * (1.0f / D_);
    float var = red2[0] * (1.0f / D_) - mu * mu;
    float inv = rsqrtf(var + 1e-6f);
    #pragma unroll
    for (int i = 0; i < 4; i++) {
        int c = t + i * 256;
        row[c] = (v[i] - mu) * inv * g[c] + bb[c];
    }
}

__global__ void copyk(float* __restrict__ dst, const float* __restrict__ src, int n) {
    int i = blockIdx.x * 256 + threadIdx.x;
    if (i < n) dst[i] = src[i];
}

// ---------------------------------------------------------------------------
extern "C" void kernel_launch(void* const* d_in, const int* in_sizes, int n_in,
                              void* d_out, int out_size) {
    const float* x_in      = (const float*)d_in[0];
    const int*   mask      = (const int*)d_in[1];
    const float* attn_bias = (const float*)d_in[2];
    const float* Wq        = (const float*)d_in[3];
    const float* Wk        = (const float*)d_in[4];
    const float* Wv        = (const float*)d_in[5];
    const float* ln1_g     = (const float*)d_in[6];
    const float* ln1_b     = (const float*)d_in[7];
    const float* W1        = (const float*)d_in[8];
    const float* b1        = (const float*)d_in[9];
    const float* W2        = (const float*)d_in[10];
    const float* b2        = (const float*)d_in[11];
    const float* ln2_g     = (const float*)d_in[12];
    const float* ln2_b     = (const float*)d_in[13];
    float* out = (float*)d_out;

    cudaFuncSetAttribute(gemm_pipe<0>, cudaFuncAttributeMaxDynamicSharedMemorySize, GEMM_SMEM);
    cudaFuncSetAttribute(gemm_pipe<1>, cudaFuncAttributeMaxDynamicSharedMemorySize, GEMM_SMEM);
    cudaFuncSetAttribute(gemm_pipe<2>, cudaFuncAttributeMaxDynamicSharedMemorySize, GEMM_SMEM);
    cudaFuncSetAttribute(fused_attn,   cudaFuncAttributeMaxDynamicSharedMemorySize, FA_SMEM);

    float *px, *pq, *pk, *pv, *po, *ph, *pf;
    cudaGetSymbolAddress((void**)&px, g_x);
    cudaGetSymbolAddress((void**)&pq, g_q);
    cudaGetSymbolAddress((void**)&pk, g_k);
    cudaGetSymbolAddress((void**)&pv, g_v);
    cudaGetSymbolAddress((void**)&po, g_o);
    cudaGetSymbolAddress((void**)&ph, g_h);
    cudaGetSymbolAddress((void**)&pf, g_f);

    const int nX = BS_ * D_;
    copyk<<<(nX + 255) / 256, 256>>>(px, x_in, nX);

    dim3 gQKV(D_ / 128, BS_ / 128, 3);     // 8 x 16 x 3
    dim3 gFF1(DFF_ / 128, BS_ / 128, 1);   // 16 x 16
    dim3 gFF2(D_ / 128, BS_ / 128, 1);     // 8 x 16
    dim3 gFA(S_ / 32, B_ * H_);            // 32 x 32 = 1024 CTAs

    for (int n = 0; n < L_; n++) {
        const float* wq = Wq + (size_t)n * D_ * D_;
        const float* wk = Wk + (size_t)n * D_ * D_;
        const float* wv = Wv + (size_t)n * D_ * D_;
        float* scores = out + (size_t)n * B_ * H_ * S_ * S_;

        gemm_pipe<0><<<gQKV, 256, GEMM_SMEM>>>(px, wq, wk, wv, nullptr,
                                               pq, pk, pv, D_, D_);

        fused_attn<<<gFA, 256, FA_SMEM>>>(attn_bias, mask, scores);

        add_ln<<<BS_, 256>>>(px, po, ln1_g + n * D_, ln1_b + n * D_);

        const float* w1 = W1 + (size_t)n * D_ * DFF_;
        const float* w2 = W2 + (size_t)n * DFF_ * D_;
        gemm_pipe<2><<<gFF1, 256, GEMM_SMEM>>>(px, w1, w1, w1, b1 + n * DFF_,
                                               ph, ph, ph, DFF_, D_);
        gemm_pipe<1><<<gFF2, 256, GEMM_SMEM>>>(ph, w2, w2, w2, b2 + n * D_,
                                               pf, pf, pf, D_, DFF_);

        add_ln<<<BS_, 256>>>(px, pf, ln2_g + n * D_, ln2_b + n * D_);
    }

    copyk<<<(nX + 255) / 256, 256>>>(out + (size_t)L_ * B_ * H_ * S_ * S_, px, nX);
}